// round 1
// baseline (speedup 1.0000x reference)
#include <cuda_runtime.h>
#include <cuda_bf16.h>
#include <cstdint>

// ---------------------------------------------------------------------------
// YOLO loss (nc=1).  B=64, N=32, A=3, grids {160,80,40}, pred [B,18,G,G].
//
// loss = 0.05 * sum_s box_sq[s]/n_pos[s]
//      +        sum_s ( pos_plus[s]/n_pos[s] + (S_all[s]-pos_neg[s])/n_neg[s] )
//
// Dense pass only reads the objectness channel (c = a*6+4) -> 1/6 of data.
// ---------------------------------------------------------------------------

#define BB 64
#define NN 32

// per-scale accumulators
__device__ double g_box[3];    // sum of squared box errors at live positives
__device__ double g_pp[3];     // sum softplus(-po) over positives
__device__ double g_pn[3];     // sum softplus(+po) over positives
__device__ double g_sall[3];   // sum softplus(po) over ALL cells
__device__ int    g_npos[3];   // number of distinct positive cells

__device__ __forceinline__ float sp(float x) {
    // softplus(x) = max(x,0) + log1p(exp(-|x|)); log(1+e) is fine (e<=1).
    return fmaxf(x, 0.0f) + __logf(1.0f + __expf(-fabsf(x)));
}

__global__ void init_kernel() {
    if (threadIdx.x == 0) {
        #pragma unroll
        for (int s = 0; s < 3; s++) {
            g_box[s] = 0.0; g_pp[s] = 0.0; g_pn[s] = 0.0; g_sall[s] = 0.0;
            g_npos[s] = 0;
        }
    }
}

// ---------------------------------------------------------------------------
// Sparse target kernel: 192 blocks (scale*64 + b), 32 threads (one per box).
// ---------------------------------------------------------------------------
__global__ void targets_kernel(const float* __restrict__ boxes,
                               const float* __restrict__ anchors,
                               const float* __restrict__ pred0,
                               const float* __restrict__ pred1,
                               const float* __restrict__ pred2) {
    const int s = blockIdx.x >> 6;          // / 64
    const int b = blockIdx.x & 63;          // % 64
    const int n = threadIdx.x;

    const int G = (s == 0) ? 160 : (s == 1) ? 80 : 40;
    const float* pred = (s == 0) ? pred0 : (s == 1) ? pred1 : pred2;
    const int HW = G * G;

    float4 bx = reinterpret_cast<const float4*>(boxes)[b * NN + n];
    float gx = bx.x * (float)G;
    float gy = bx.y * (float)G;
    float gw = bx.z * (float)G;
    float gh = bx.w * (float)G;
    int gi = (int)gx;
    int gj = (int)gy;

    // anchor matching: argmax over a of prod(min(r,1/r)), first-max tiebreak
    float bestIou = -1.0f;
    int best = 0;
    float aw = 1.0f, ah = 1.0f;
    #pragma unroll
    for (int a = 0; a < 3; a++) {
        float Aw = anchors[s * 6 + a * 2 + 0];
        float Ah = anchors[s * 6 + a * 2 + 1];
        float rw = __fdiv_rn(Aw, gw);
        float rh = __fdiv_rn(Ah, gh);
        float iw = fminf(rw, __fdiv_rn(1.0f, rw));
        float ih = fminf(rh, __fdiv_rn(1.0f, rh));
        float iou = iw * ih;
        if (iou > bestIou) { bestIou = iou; best = a; aw = Aw; ah = Ah; }
    }

    // dedup: last write wins -> entry n is live iff no later n' has same key
    __shared__ int keys[NN];
    int key = (best * G + gj) * G + gi;
    keys[n] = key;
    __syncwarp();
    bool live = true;
    for (int m = n + 1; m < NN; m++) {
        if (keys[m] == key) { live = false; break; }
    }

    float sq = 0.0f, spp = 0.0f, spm = 0.0f;
    int cnt = 0;
    if (live) {
        size_t base = (size_t)(b * 18 + best * 6) * HW + (size_t)gj * G + gi;
        float p0 = __ldg(pred + base);
        float p1 = __ldg(pred + base + (size_t)HW);
        float p2 = __ldg(pred + base + (size_t)2 * HW);
        float p3 = __ldg(pred + base + (size_t)3 * HW);
        float p4 = __ldg(pred + base + (size_t)4 * HW);

        float tx = gx - (float)gi;
        float ty = gy - (float)gj;
        float tw = logf(__fdiv_rn(gw, aw) + 1e-16f);
        float th = logf(__fdiv_rn(gh, ah) + 1e-16f);

        float d0 = p0 - tx, d1 = p1 - ty, d2 = p2 - tw, d3 = p3 - th;
        sq  = d0 * d0 + d1 * d1 + d2 * d2 + d3 * d3;
        spm = sp(-p4);   // positive target term softplus(-x)
        spp = sp(p4);    // correction to subtract from S_all
        cnt = 1;
    }

    // warp reduce
    #pragma unroll
    for (int o = 16; o > 0; o >>= 1) {
        sq  += __shfl_down_sync(0xffffffffu, sq,  o);
        spm += __shfl_down_sync(0xffffffffu, spm, o);
        spp += __shfl_down_sync(0xffffffffu, spp, o);
        cnt += __shfl_down_sync(0xffffffffu, cnt, o);
    }
    if (n == 0) {
        atomicAdd(&g_box[s], (double)sq);
        atomicAdd(&g_pp[s],  (double)spm);
        atomicAdd(&g_pn[s],  (double)spp);
        atomicAdd(&g_npos[s], cnt);
    }
}

// ---------------------------------------------------------------------------
// Dense objectness pass: sum softplus over channel 4 of each anchor.
// float4 per thread; blocks never straddle scales (boundaries are /256).
//   scale0: float4 [0, 1228800)        -> blocks [0, 4800)
//   scale1: float4 [1228800, 1536000)  -> blocks [4800, 6000)
//   scale2: float4 [1536000, 1612800)  -> blocks [6000, 6300)
// ---------------------------------------------------------------------------
template <int HW4>
__device__ __forceinline__ float obj_sum4(const float* __restrict__ pred, int local) {
    int b   = local / (3 * HW4);
    int r   = local - b * 3 * HW4;
    int a   = r / HW4;
    int pos = r - a * HW4;
    const float4* p4 = reinterpret_cast<const float4*>(pred);
    float4 v = __ldg(p4 + (size_t)(b * 18 + a * 6 + 4) * HW4 + pos);
    return sp(v.x) + sp(v.y) + sp(v.z) + sp(v.w);
}

__global__ void objsum_kernel(const float* __restrict__ pred0,
                              const float* __restrict__ pred1,
                              const float* __restrict__ pred2) {
    const int t = blockIdx.x * blockDim.x + threadIdx.x;
    int s;
    float v;
    if (blockIdx.x < 4800) {
        s = 0; v = obj_sum4<6400>(pred0, t);
    } else if (blockIdx.x < 6000) {
        s = 1; v = obj_sum4<1600>(pred1, t - 1228800);
    } else {
        s = 2; v = obj_sum4<400>(pred2, t - 1536000);
    }

    // block reduction
    #pragma unroll
    for (int o = 16; o > 0; o >>= 1)
        v += __shfl_down_sync(0xffffffffu, v, o);
    __shared__ float warpsum[8];
    int lane = threadIdx.x & 31;
    int wid  = threadIdx.x >> 5;
    if (lane == 0) warpsum[wid] = v;
    __syncthreads();
    if (wid == 0) {
        v = (lane < 8) ? warpsum[lane] : 0.0f;
        #pragma unroll
        for (int o = 4; o > 0; o >>= 1)
            v += __shfl_down_sync(0xffffffffu, v, o);
        if (lane == 0) atomicAdd(&g_sall[s], (double)v);
    }
}

__global__ void finalize_kernel(float* __restrict__ out) {
    if (threadIdx.x == 0) {
        const double cells[3] = {4915200.0, 1228800.0, 307200.0}; // B*A*H*W
        double loss = 0.0;
        #pragma unroll
        for (int s = 0; s < 3; s++) {
            double np = (double)g_npos[s];
            double nn = cells[s] - np;
            loss += 0.05 * g_box[s] / np          // LAMBDA_BOX * loss_box
                  + g_pp[s] / np                  // positive obj term
                  + (g_sall[s] - g_pn[s]) / nn;   // negative obj term
        }
        out[0] = (float)loss;
    }
}

extern "C" void kernel_launch(void* const* d_in, const int* in_sizes, int n_in,
                              void* d_out, int out_size) {
    (void)in_sizes; (void)n_in; (void)out_size;
    const float* pred0   = (const float*)d_in[0];
    const float* pred1   = (const float*)d_in[1];
    const float* pred2   = (const float*)d_in[2];
    const float* boxes   = (const float*)d_in[3];
    // d_in[4] = labels (unused, nc==1)
    const float* anchors = (const float*)d_in[5];
    float* out = (float*)d_out;

    init_kernel<<<1, 32>>>();
    targets_kernel<<<192, 32>>>(boxes, anchors, pred0, pred1, pred2);
    objsum_kernel<<<6300, 256>>>(pred0, pred1, pred2);
    finalize_kernel<<<1, 32>>>(out);
}

// round 2
// speedup vs baseline: 1.0058x; 1.0058x over previous
#include <cuda_runtime.h>
#include <cuda_bf16.h>
#include <cstdint>

// ---------------------------------------------------------------------------
// YOLO loss (nc=1).  B=64, N=32, A=3, grids {160,80,40}, pred [B,18,G,G].
//
// loss = 0.05 * sum_s box_sq[s]/n_pos[s]
//      +        sum_s ( pos_plus[s]/n_pos[s] + (S_all[s]-pos_neg[s])/n_neg[s] )
//
// Single fused kernel:
//   blocks [0,3150): dense objectness softplus sum (channel a*6+4 only, 1/6 of data)
//   blocks [3150,3174): 192 warp-tasks = (scale,batch) target matching
//   last block to finish: finalize + reset accumulators (ready for next replay)
// ---------------------------------------------------------------------------

#define NN 32
#define OBJ_BLOCKS 3150           // 2400 (s0) + 600 (s1) + 150 (s2), 512 float4/block
#define TGT_BLOCKS 24             // 24 * 8 warps = 192 (s,b) tasks
#define TOTAL_BLOCKS (OBJ_BLOCKS + TGT_BLOCKS)

// accumulators: zero at module load; finalizer resets them after each use
__device__ double   g_box[3];
__device__ double   g_pp[3];
__device__ double   g_pn[3];
__device__ double   g_sall[3];
__device__ int      g_npos[3];
__device__ unsigned g_ticket;

__device__ __forceinline__ float sp(float x) {
    // softplus(x) = max(x,0) + log(1+exp(-|x|)); arg of log in [1,2]
    return fmaxf(x, 0.0f) + __logf(1.0f + __expf(-fabsf(x)));
}

template <int HW4>
__device__ __forceinline__ float obj_sum4(const float* __restrict__ pred, int local) {
    int b   = local / (3 * HW4);
    int r   = local - b * 3 * HW4;
    int a   = r / HW4;
    int pos = r - a * HW4;
    const float4* p4 = reinterpret_cast<const float4*>(pred);
    float4 v = __ldg(p4 + (size_t)(b * 18 + a * 6 + 4) * HW4 + pos);
    return sp(v.x) + sp(v.y) + sp(v.z) + sp(v.w);
}

__global__ void __launch_bounds__(256) yolo_fused_kernel(
        const float* __restrict__ pred0,
        const float* __restrict__ pred1,
        const float* __restrict__ pred2,
        const float* __restrict__ boxes,
        const float* __restrict__ anchors,
        float* __restrict__ out) {
    const int bid  = blockIdx.x;
    const int tid  = threadIdx.x;
    const int lane = tid & 31;
    const int wid  = tid >> 5;

    __shared__ int   keys[8][NN];
    __shared__ float warpsum[8];
    __shared__ bool  s_last;

    if (bid < OBJ_BLOCKS) {
        // ---------------- dense objectness pass: 2 float4 per thread ----------------
        float v;
        if (bid < 2400) {
            int base = bid * 512;
            v = obj_sum4<6400>(pred0, base + tid) + obj_sum4<6400>(pred0, base + 256 + tid);
        } else if (bid < 3000) {
            int base = (bid - 2400) * 512;
            v = obj_sum4<1600>(pred1, base + tid) + obj_sum4<1600>(pred1, base + 256 + tid);
        } else {
            int base = (bid - 3000) * 512;
            v = obj_sum4<400>(pred2, base + tid) + obj_sum4<400>(pred2, base + 256 + tid);
        }
        const int s = (bid < 2400) ? 0 : (bid < 3000) ? 1 : 2;

        #pragma unroll
        for (int o = 16; o > 0; o >>= 1)
            v += __shfl_down_sync(0xffffffffu, v, o);
        if (lane == 0) warpsum[wid] = v;
        __syncthreads();
        if (wid == 0) {
            v = (lane < 8) ? warpsum[lane] : 0.0f;
            #pragma unroll
            for (int o = 4; o > 0; o >>= 1)
                v += __shfl_down_sync(0xffffffffu, v, o);
            if (lane == 0) atomicAdd(&g_sall[s], (double)v);
        }
    } else {
        // ---------------- sparse target pass: one (scale,batch) per warp ----------------
        const int task = (bid - OBJ_BLOCKS) * 8 + wid;   // 0..191
        const int s = task >> 6;
        const int b = task & 63;
        const int n = lane;

        const int G = (s == 0) ? 160 : (s == 1) ? 80 : 40;
        const float* pred = (s == 0) ? pred0 : (s == 1) ? pred1 : pred2;
        const int HW = G * G;

        float4 bx = reinterpret_cast<const float4*>(boxes)[b * NN + n];
        float gx = bx.x * (float)G;
        float gy = bx.y * (float)G;
        float gw = bx.z * (float)G;
        float gh = bx.w * (float)G;
        int gi = (int)gx;
        int gj = (int)gy;

        // anchor matching: argmax over a of prod(min(r,1/r)), first-max tiebreak
        float bestIou = -1.0f;
        float aw = 1.0f, ah = 1.0f;
        int best = 0;
        #pragma unroll
        for (int a = 0; a < 3; a++) {
            float Aw = anchors[s * 6 + a * 2 + 0];
            float Ah = anchors[s * 6 + a * 2 + 1];
            float rw = __fdiv_rn(Aw, gw);
            float rh = __fdiv_rn(Ah, gh);
            float iw = fminf(rw, __fdiv_rn(1.0f, rw));
            float ih = fminf(rh, __fdiv_rn(1.0f, rh));
            float iou = iw * ih;
            if (iou > bestIou) { bestIou = iou; best = a; aw = Aw; ah = Ah; }
        }

        // dedup: last write wins -> entry n live iff no later n' has same key
        int key = (best * G + gj) * G + gi;
        keys[wid][n] = key;
        __syncwarp();
        bool live = true;
        for (int m = n + 1; m < NN; m++)
            if (keys[wid][m] == key) { live = false; break; }

        float sq = 0.0f, spp = 0.0f, spm = 0.0f;
        int cnt = 0;
        if (live) {
            size_t base = (size_t)(b * 18 + best * 6) * HW + (size_t)gj * G + gi;
            float p0 = __ldg(pred + base);
            float p1 = __ldg(pred + base + (size_t)HW);
            float p2 = __ldg(pred + base + (size_t)2 * HW);
            float p3 = __ldg(pred + base + (size_t)3 * HW);
            float p4 = __ldg(pred + base + (size_t)4 * HW);

            float tx = gx - (float)gi;
            float ty = gy - (float)gj;
            float tw = logf(__fdiv_rn(gw, aw) + 1e-16f);
            float th = logf(__fdiv_rn(gh, ah) + 1e-16f);

            float d0 = p0 - tx, d1 = p1 - ty, d2 = p2 - tw, d3 = p3 - th;
            sq  = d0 * d0 + d1 * d1 + d2 * d2 + d3 * d3;
            spm = sp(-p4);
            spp = sp(p4);
            cnt = 1;
        }

        #pragma unroll
        for (int o = 16; o > 0; o >>= 1) {
            sq  += __shfl_down_sync(0xffffffffu, sq,  o);
            spm += __shfl_down_sync(0xffffffffu, spm, o);
            spp += __shfl_down_sync(0xffffffffu, spp, o);
            cnt += __shfl_down_sync(0xffffffffu, cnt, o);
        }
        if (n == 0) {
            atomicAdd(&g_box[s], (double)sq);
            atomicAdd(&g_pp[s],  (double)spm);
            atomicAdd(&g_pn[s],  (double)spp);
            atomicAdd(&g_npos[s], cnt);
        }
        __syncthreads();   // keep block lockstep before the ticket
    }

    // ---------------- last-block finalize ----------------
    __threadfence();
    if (tid == 0) {
        unsigned t = atomicAdd(&g_ticket, 1u);
        s_last = (t == TOTAL_BLOCKS - 1);
    }
    __syncthreads();
    if (s_last && tid == 0) {
        __threadfence();
        const double cells[3] = {4915200.0, 1228800.0, 307200.0}; // B*A*H*W
        double loss = 0.0;
        #pragma unroll
        for (int s = 0; s < 3; s++) {
            double np = (double)((volatile int*)g_npos)[s];
            double nn = cells[s] - np;
            double vbox  = ((volatile double*)g_box)[s];
            double vpp   = ((volatile double*)g_pp)[s];
            double vpn   = ((volatile double*)g_pn)[s];
            double vsall = ((volatile double*)g_sall)[s];
            loss += 0.05 * vbox / np + vpp / np + (vsall - vpn) / nn;
            // reset for the next graph replay
            g_box[s] = 0.0; g_pp[s] = 0.0; g_pn[s] = 0.0; g_sall[s] = 0.0;
            g_npos[s] = 0;
        }
        g_ticket = 0u;
        out[0] = (float)loss;
        __threadfence();
    }
}

extern "C" void kernel_launch(void* const* d_in, const int* in_sizes, int n_in,
                              void* d_out, int out_size) {
    (void)in_sizes; (void)n_in; (void)out_size;
    const float* pred0   = (const float*)d_in[0];
    const float* pred1   = (const float*)d_in[1];
    const float* pred2   = (const float*)d_in[2];
    const float* boxes   = (const float*)d_in[3];
    // d_in[4] = labels (unused, nc==1)
    const float* anchors = (const float*)d_in[5];
    float* out = (float*)d_out;

    yolo_fused_kernel<<<TOTAL_BLOCKS, 256>>>(pred0, pred1, pred2, boxes, anchors, out);
}

// round 3
// speedup vs baseline: 1.3342x; 1.3265x over previous
#include <cuda_runtime.h>
#include <cuda_bf16.h>
#include <cstdint>

// ---------------------------------------------------------------------------
// YOLO loss (nc=1).  B=64, N=32, A=3, grids {160,80,40}, pred [B,18,G,G].
//
// loss = 0.05 * sum_s box_sq[s]/n_pos[s]
//      +        sum_s ( pos_plus[s]/n_pos[s] + (S_all[s]-pos_neg[s])/n_neg[s] )
//
// One launch:
//   blocks [0,24):      192 warp-tasks = (scale,batch) target matching (atomics, few)
//   blocks [24,654):    dense objectness softplus sum, 10 float4/thread, MLP=5,
//                       per-block double partial -> g_part[] (NO atomics)
//   last block (ticket): reduce partials, combine, write out, reset state
// ---------------------------------------------------------------------------

#define NN 32
#define NB0 480                 // scale0: 1228800 f4 / (480*256) = 10 per thread
#define NB1 120                 // scale1:  307200 f4 / (120*256) = 10 per thread
#define NB2 30                  // scale2:   76800 f4 / ( 30*256) = 10 per thread
#define TGT_BLOCKS 24
#define DENSE_BLOCKS (NB0 + NB1 + NB2)          // 630
#define TOTAL_BLOCKS (TGT_BLOCKS + DENSE_BLOCKS) // 654

// zero at module load; finalizer resets the mutable ones each replay
__device__ double   g_part[DENSE_BLOCKS];
__device__ double   g_box[3], g_pp[3], g_pn[3];
__device__ int      g_npos[3];
__device__ unsigned g_ticket;

__device__ __forceinline__ float sp(float x) {
    // softplus(x) = max(x,0) + log(1+exp(-|x|)); log arg in [1,2]
    return fmaxf(x, 0.0f) + __logf(1.0f + __expf(-fabsf(x)));
}

template <int HW4, int NBLK>
__device__ __forceinline__ float dense_sum(const float* __restrict__ pred,
                                           int localb, int tid) {
    const float4* p4 = reinterpret_cast<const float4*>(pred);
    const int base   = localb * 256 + tid;
    const int STRIDE = NBLK * 256;
    float acc = 0.0f;
    #pragma unroll
    for (int h = 0; h < 2; h++) {
        float4 v[5];
        #pragma unroll
        for (int k = 0; k < 5; k++) {
            int idx = base + (h * 5 + k) * STRIDE;
            int b   = idx / (3 * HW4);
            int r   = idx - b * 3 * HW4;
            int a   = r / HW4;
            int pos = r - a * HW4;
            v[k] = __ldg(p4 + (size_t)(b * 18 + a * 6 + 4) * HW4 + pos);
        }
        #pragma unroll
        for (int k = 0; k < 5; k++)
            acc += sp(v[k].x) + sp(v[k].y) + sp(v[k].z) + sp(v[k].w);
    }
    return acc;
}

__global__ void __launch_bounds__(256) yolo_fused_kernel(
        const float* __restrict__ pred0,
        const float* __restrict__ pred1,
        const float* __restrict__ pred2,
        const float* __restrict__ boxes,
        const float* __restrict__ anchors,
        float* __restrict__ out) {
    const int bid  = blockIdx.x;
    const int tid  = threadIdx.x;
    const int lane = tid & 31;
    const int wid  = tid >> 5;

    __shared__ int    keys[8][NN];
    __shared__ float  warpsum[8];
    __shared__ double dsum[3][8];
    __shared__ bool   s_last;

    if (bid >= TGT_BLOCKS) {
        // ---------------- dense objectness pass ----------------
        const int d = bid - TGT_BLOCKS;
        float v;
        if (d < NB0)            v = dense_sum<6400, NB0>(pred0, d, tid);
        else if (d < NB0 + NB1) v = dense_sum<1600, NB1>(pred1, d - NB0, tid);
        else                    v = dense_sum< 400, NB2>(pred2, d - NB0 - NB1, tid);

        #pragma unroll
        for (int o = 16; o > 0; o >>= 1)
            v += __shfl_down_sync(0xffffffffu, v, o);
        if (lane == 0) warpsum[wid] = v;
        __syncthreads();
        if (tid == 0) {
            double t = 0.0;
            #pragma unroll
            for (int w = 0; w < 8; w++) t += (double)warpsum[w];
            g_part[d] = t;
            __threadfence();
        }
    } else {
        // ---------------- sparse target pass: one (scale,batch) per warp ----------------
        const int task = bid * 8 + wid;          // 0..191
        const int s = task >> 6;
        const int b = task & 63;
        const int n = lane;

        const int G = (s == 0) ? 160 : (s == 1) ? 80 : 40;
        const float* pred = (s == 0) ? pred0 : (s == 1) ? pred1 : pred2;
        const int HW = G * G;

        float4 bx = reinterpret_cast<const float4*>(boxes)[b * NN + n];
        float gx = bx.x * (float)G;
        float gy = bx.y * (float)G;
        float gw = bx.z * (float)G;
        float gh = bx.w * (float)G;
        int gi = (int)gx;
        int gj = (int)gy;

        // anchor matching: argmax over a of prod(min(r,1/r)), first-max tiebreak
        float bestIou = -1.0f;
        float aw = 1.0f, ah = 1.0f;
        int best = 0;
        #pragma unroll
        for (int a = 0; a < 3; a++) {
            float Aw = anchors[s * 6 + a * 2 + 0];
            float Ah = anchors[s * 6 + a * 2 + 1];
            float rw = __fdiv_rn(Aw, gw);
            float rh = __fdiv_rn(Ah, gh);
            float iw = fminf(rw, __fdiv_rn(1.0f, rw));
            float ih = fminf(rh, __fdiv_rn(1.0f, rh));
            float iou = iw * ih;
            if (iou > bestIou) { bestIou = iou; best = a; aw = Aw; ah = Ah; }
        }

        // dedup: last write wins -> entry n live iff no later n' has same key
        int key = (best * G + gj) * G + gi;
        keys[wid][n] = key;
        __syncwarp();
        bool live = true;
        for (int m = n + 1; m < NN; m++)
            if (keys[wid][m] == key) { live = false; break; }

        float sq = 0.0f, spp = 0.0f, spm = 0.0f;
        int cnt = 0;
        if (live) {
            size_t base = (size_t)(b * 18 + best * 6) * HW + (size_t)gj * G + gi;
            float p0 = __ldg(pred + base);
            float p1 = __ldg(pred + base + (size_t)HW);
            float p2 = __ldg(pred + base + (size_t)2 * HW);
            float p3 = __ldg(pred + base + (size_t)3 * HW);
            float p4 = __ldg(pred + base + (size_t)4 * HW);

            float tx = gx - (float)gi;
            float ty = gy - (float)gj;
            float tw = logf(__fdiv_rn(gw, aw) + 1e-16f);
            float th = logf(__fdiv_rn(gh, ah) + 1e-16f);

            float d0 = p0 - tx, d1 = p1 - ty, d2 = p2 - tw, d3 = p3 - th;
            sq  = d0 * d0 + d1 * d1 + d2 * d2 + d3 * d3;
            spm = sp(-p4);
            spp = sp(p4);
            cnt = 1;
        }

        #pragma unroll
        for (int o = 16; o > 0; o >>= 1) {
            sq  += __shfl_down_sync(0xffffffffu, sq,  o);
            spm += __shfl_down_sync(0xffffffffu, spm, o);
            spp += __shfl_down_sync(0xffffffffu, spp, o);
            cnt += __shfl_down_sync(0xffffffffu, cnt, o);
        }
        if (n == 0) {
            atomicAdd(&g_box[s], (double)sq);
            atomicAdd(&g_pp[s],  (double)spm);
            atomicAdd(&g_pn[s],  (double)spp);
            atomicAdd(&g_npos[s], cnt);
            __threadfence();   // writer fences its own atomics
        }
        __syncthreads();
    }

    // ---------------- last-block finalize ----------------
    if (tid == 0) {
        unsigned t = atomicAdd(&g_ticket, 1u);
        s_last = (t == TOTAL_BLOCKS - 1);
    }
    __syncthreads();
    if (s_last) {
        __threadfence();
        // parallel per-scale reduction of dense partials (doubles, no atomics)
        double v0 = 0.0, v1 = 0.0, v2 = 0.0;
        for (int i = tid; i < NB0; i += 256) v0 += ((volatile double*)g_part)[i];
        for (int i = tid; i < NB1; i += 256) v1 += ((volatile double*)g_part)[NB0 + i];
        for (int i = tid; i < NB2; i += 256) v2 += ((volatile double*)g_part)[NB0 + NB1 + i];
        #pragma unroll
        for (int o = 16; o > 0; o >>= 1) {
            v0 += __shfl_down_sync(0xffffffffu, v0, o);
            v1 += __shfl_down_sync(0xffffffffu, v1, o);
            v2 += __shfl_down_sync(0xffffffffu, v2, o);
        }
        if (lane == 0) { dsum[0][wid] = v0; dsum[1][wid] = v1; dsum[2][wid] = v2; }
        __syncthreads();
        if (tid == 0) {
            double sall[3] = {0.0, 0.0, 0.0};
            #pragma unroll
            for (int w = 0; w < 8; w++) {
                sall[0] += dsum[0][w]; sall[1] += dsum[1][w]; sall[2] += dsum[2][w];
            }
            const double cells[3] = {4915200.0, 1228800.0, 307200.0}; // B*A*H*W
            double loss = 0.0;
            #pragma unroll
            for (int s = 0; s < 3; s++) {
                double np = (double)((volatile int*)g_npos)[s];
                double nn = cells[s] - np;
                double vbox = ((volatile double*)g_box)[s];
                double vpp  = ((volatile double*)g_pp)[s];
                double vpn  = ((volatile double*)g_pn)[s];
                loss += 0.05 * vbox / np + vpp / np + (sall[s] - vpn) / nn;
                // reset for next graph replay
                g_box[s] = 0.0; g_pp[s] = 0.0; g_pn[s] = 0.0;
                g_npos[s] = 0;
            }
            g_ticket = 0u;
            out[0] = (float)loss;
            __threadfence();
        }
    }
}

extern "C" void kernel_launch(void* const* d_in, const int* in_sizes, int n_in,
                              void* d_out, int out_size) {
    (void)in_sizes; (void)n_in; (void)out_size;
    const float* pred0   = (const float*)d_in[0];
    const float* pred1   = (const float*)d_in[1];
    const float* pred2   = (const float*)d_in[2];
    const float* boxes   = (const float*)d_in[3];
    // d_in[4] = labels (unused, nc==1)
    const float* anchors = (const float*)d_in[5];
    float* out = (float*)d_out;

    yolo_fused_kernel<<<TOTAL_BLOCKS, 256>>>(pred0, pred1, pred2, boxes, anchors, out);
}

// round 4
// speedup vs baseline: 1.3359x; 1.0013x over previous
#include <cuda_runtime.h>
#include <cuda_bf16.h>
#include <cstdint>

// ---------------------------------------------------------------------------
// YOLO loss (nc=1).  B=64, N=32, A=3, grids {160,80,40}, pred [B,18,G,G].
//
// loss = 0.05 * sum_s box_sq[s]/n_pos[s]
//      +        sum_s ( pos_plus[s]/n_pos[s] + (S_all[s]-pos_neg[s])/n_neg[s] )
//
// One launch:
//   blocks [0,24):        192 warp-tasks = (scale,batch) target matching
//   blocks [24,24+1260):  dense objectness softplus sum; each block owns a
//                         contiguous 1280-float4 range of the gathered
//                         obj-channel space (5 float4/thread, all loads
//                         independent); per-block double partial -> g_part[]
//   last block (ticket):  reduce partials, combine, write out, reset state
// ---------------------------------------------------------------------------

#define NN 32
#define NB0 960                  // scale0: 1228800 f4 / 1280
#define NB1 240                  // scale1:  307200 f4 / 1280
#define NB2 60                   // scale2:   76800 f4 / 1280
#define TGT_BLOCKS 24
#define DENSE_BLOCKS (NB0 + NB1 + NB2)            // 1260
#define TOTAL_BLOCKS (TGT_BLOCKS + DENSE_BLOCKS)  // 1284

// zero at module load; finalizer resets the mutable ones each replay
__device__ double   g_part[DENSE_BLOCKS];
__device__ double   g_box[3], g_pp[3], g_pn[3];
__device__ int      g_npos[3];
__device__ unsigned g_ticket;

__device__ __forceinline__ float sp(float x) {
    return fmaxf(x, 0.0f) + __logf(1.0f + __expf(-fabsf(x)));
}

// gathered obj-channel index -> physical float4 index:
//   idx = p*HW4 + pos, plane p -> channel 6p+4  =>  phys = 6*idx + 4*HW4 - 5*pos
template <int HW4>
__device__ __forceinline__ const float4* obj_ptr(const float4* __restrict__ p4, int idx) {
    int pos = idx - (idx / HW4) * HW4;
    return p4 + (size_t)(6 * idx + 4 * HW4 - 5 * pos);
}

template <int HW4>
__device__ __forceinline__ float dense_sum(const float* __restrict__ pred,
                                           int localb, int tid) {
    const float4* p4 = reinterpret_cast<const float4*>(pred);
    const int base = localb * 1280 + tid;

    // 5 independent loads, all issued before any compute
    float4 v0 = __ldg(obj_ptr<HW4>(p4, base));
    float4 v1 = __ldg(obj_ptr<HW4>(p4, base + 256));
    float4 v2 = __ldg(obj_ptr<HW4>(p4, base + 512));
    float4 v3 = __ldg(obj_ptr<HW4>(p4, base + 768));
    float4 v4 = __ldg(obj_ptr<HW4>(p4, base + 1024));

    // softplus(x) = max(x,0) + ln2 * log2(1 + exp(-|x|)); split accumulators
    float alin = 0.0f, alog = 0.0f;
    float4 vv[5] = {v0, v1, v2, v3, v4};
    #pragma unroll
    for (int k = 0; k < 5; k++) {
        const float xs[4] = {vv[k].x, vv[k].y, vv[k].z, vv[k].w};
        #pragma unroll
        for (int e = 0; e < 4; e++) {
            float x = xs[e];
            alin += fmaxf(x, 0.0f);
            alog += __log2f(1.0f + __expf(-fabsf(x)));
        }
    }
    return alin + 0.69314718055994531f * alog;
}

__global__ void yolo_fused_kernel(
        const float* __restrict__ pred0,
        const float* __restrict__ pred1,
        const float* __restrict__ pred2,
        const float* __restrict__ boxes,
        const float* __restrict__ anchors,
        float* __restrict__ out) {
    const int bid  = blockIdx.x;
    const int tid  = threadIdx.x;
    const int lane = tid & 31;
    const int wid  = tid >> 5;

    __shared__ int    keys[8][NN];
    __shared__ float  warpsum[8];
    __shared__ double dsum[3][8];
    __shared__ bool   s_last;

    if (bid >= TGT_BLOCKS) {
        // ---------------- dense objectness pass ----------------
        const int d = bid - TGT_BLOCKS;
        float v;
        if (d < NB0)            v = dense_sum<6400>(pred0, d, tid);
        else if (d < NB0 + NB1) v = dense_sum<1600>(pred1, d - NB0, tid);
        else                    v = dense_sum< 400>(pred2, d - NB0 - NB1, tid);

        #pragma unroll
        for (int o = 16; o > 0; o >>= 1)
            v += __shfl_down_sync(0xffffffffu, v, o);
        if (lane == 0) warpsum[wid] = v;
        __syncthreads();
        if (tid == 0) {
            double t = 0.0;
            #pragma unroll
            for (int w = 0; w < 8; w++) t += (double)warpsum[w];
            g_part[d] = t;
            __threadfence();
        }
    } else {
        // ---------------- sparse target pass: one (scale,batch) per warp ----------------
        const int task = bid * 8 + wid;          // 0..191
        const int s = task >> 6;
        const int b = task & 63;
        const int n = lane;

        const int G = (s == 0) ? 160 : (s == 1) ? 80 : 40;
        const float* pred = (s == 0) ? pred0 : (s == 1) ? pred1 : pred2;
        const int HW = G * G;

        float4 bx = reinterpret_cast<const float4*>(boxes)[b * NN + n];
        float gx = bx.x * (float)G;
        float gy = bx.y * (float)G;
        float gw = bx.z * (float)G;
        float gh = bx.w * (float)G;
        int gi = (int)gx;
        int gj = (int)gy;

        // anchor matching: argmax over a of prod(min(r,1/r)), first-max tiebreak
        float bestIou = -1.0f;
        float aw = 1.0f, ah = 1.0f;
        int best = 0;
        #pragma unroll
        for (int a = 0; a < 3; a++) {
            float Aw = anchors[s * 6 + a * 2 + 0];
            float Ah = anchors[s * 6 + a * 2 + 1];
            float rw = __fdiv_rn(Aw, gw);
            float rh = __fdiv_rn(Ah, gh);
            float iw = fminf(rw, __fdiv_rn(1.0f, rw));
            float ih = fminf(rh, __fdiv_rn(1.0f, rh));
            float iou = iw * ih;
            if (iou > bestIou) { bestIou = iou; best = a; aw = Aw; ah = Ah; }
        }

        // dedup: last write wins -> entry n live iff no later n' has same key
        int key = (best * G + gj) * G + gi;
        keys[wid][n] = key;
        __syncwarp();
        bool live = true;
        for (int m = n + 1; m < NN; m++)
            if (keys[wid][m] == key) { live = false; break; }

        float sq = 0.0f, spp = 0.0f, spm = 0.0f;
        int cnt = 0;
        if (live) {
            size_t base = (size_t)(b * 18 + best * 6) * HW + (size_t)gj * G + gi;
            float p0 = __ldg(pred + base);
            float p1 = __ldg(pred + base + (size_t)HW);
            float p2 = __ldg(pred + base + (size_t)2 * HW);
            float p3 = __ldg(pred + base + (size_t)3 * HW);
            float p4 = __ldg(pred + base + (size_t)4 * HW);

            float tx = gx - (float)gi;
            float ty = gy - (float)gj;
            float tw = logf(__fdiv_rn(gw, aw) + 1e-16f);
            float th = logf(__fdiv_rn(gh, ah) + 1e-16f);

            float d0 = p0 - tx, d1 = p1 - ty, d2 = p2 - tw, d3 = p3 - th;
            sq  = d0 * d0 + d1 * d1 + d2 * d2 + d3 * d3;
            spm = sp(-p4);
            spp = sp(p4);
            cnt = 1;
        }

        #pragma unroll
        for (int o = 16; o > 0; o >>= 1) {
            sq  += __shfl_down_sync(0xffffffffu, sq,  o);
            spm += __shfl_down_sync(0xffffffffu, spm, o);
            spp += __shfl_down_sync(0xffffffffu, spp, o);
            cnt += __shfl_down_sync(0xffffffffu, cnt, o);
        }
        if (n == 0) {
            atomicAdd(&g_box[s], (double)sq);
            atomicAdd(&g_pp[s],  (double)spm);
            atomicAdd(&g_pn[s],  (double)spp);
            atomicAdd(&g_npos[s], cnt);
            __threadfence();
        }
        __syncthreads();
    }

    // ---------------- last-block finalize ----------------
    if (tid == 0) {
        unsigned t = atomicAdd(&g_ticket, 1u);
        s_last = (t == TOTAL_BLOCKS - 1);
    }
    __syncthreads();
    if (s_last) {
        __threadfence();
        double v0 = 0.0, v1 = 0.0, v2 = 0.0;
        for (int i = tid; i < NB0; i += 256) v0 += ((volatile double*)g_part)[i];
        for (int i = tid; i < NB1; i += 256) v1 += ((volatile double*)g_part)[NB0 + i];
        if (tid < NB2) v2 = ((volatile double*)g_part)[NB0 + NB1 + tid];
        #pragma unroll
        for (int o = 16; o > 0; o >>= 1) {
            v0 += __shfl_down_sync(0xffffffffu, v0, o);
            v1 += __shfl_down_sync(0xffffffffu, v1, o);
            v2 += __shfl_down_sync(0xffffffffu, v2, o);
        }
        if (lane == 0) { dsum[0][wid] = v0; dsum[1][wid] = v1; dsum[2][wid] = v2; }
        __syncthreads();
        if (tid == 0) {
            double sall[3] = {0.0, 0.0, 0.0};
            #pragma unroll
            for (int w = 0; w < 8; w++) {
                sall[0] += dsum[0][w]; sall[1] += dsum[1][w]; sall[2] += dsum[2][w];
            }
            const double cells[3] = {4915200.0, 1228800.0, 307200.0}; // B*A*H*W
            double loss = 0.0;
            #pragma unroll
            for (int s = 0; s < 3; s++) {
                double np = (double)((volatile int*)g_npos)[s];
                double nn = cells[s] - np;
                double vbox = ((volatile double*)g_box)[s];
                double vpp  = ((volatile double*)g_pp)[s];
                double vpn  = ((volatile double*)g_pn)[s];
                loss += 0.05 * vbox / np + vpp / np + (sall[s] - vpn) / nn;
                g_box[s] = 0.0; g_pp[s] = 0.0; g_pn[s] = 0.0;
                g_npos[s] = 0;
            }
            g_ticket = 0u;
            out[0] = (float)loss;
            __threadfence();
        }
    }
}

extern "C" void kernel_launch(void* const* d_in, const int* in_sizes, int n_in,
                              void* d_out, int out_size) {
    (void)in_sizes; (void)n_in; (void)out_size;
    const float* pred0   = (const float*)d_in[0];
    const float* pred1   = (const float*)d_in[1];
    const float* pred2   = (const float*)d_in[2];
    const float* boxes   = (const float*)d_in[3];
    // d_in[4] = labels (unused, nc==1)
    const float* anchors = (const float*)d_in[5];
    float* out = (float*)d_out;

    yolo_fused_kernel<<<TOTAL_BLOCKS, 256>>>(pred0, pred1, pred2, boxes, anchors, out);
}